// round 14
// baseline (speedup 1.0000x reference)
#include <cuda_runtime.h>

// ---------------------------------------------------------------------------
// 4-qubit, 5-layer data-reuploading circuit, one sample per thread.
// State: 16 complex amplitudes, each packed (re,im) into a 64-bit f32x2 reg
// pair. All gate math uses Blackwell packed fma.rn.f32x2 / mul.rn.f32x2.
// Qubit q (wire 0 = MSB) maps to index bit mask (8 >> q).
// ---------------------------------------------------------------------------

typedef unsigned long long u64;

__device__ __forceinline__ u64 pk(float x, float y) {
    u64 r; asm("mov.b64 %0,{%1,%2};" : "=l"(r) : "f"(x), "f"(y)); return r;
}
__device__ __forceinline__ void upk(u64 v, float& x, float& y) {
    asm("mov.b64 {%0,%1},%2;" : "=f"(x), "=f"(y) : "l"(v));
}
__device__ __forceinline__ u64 fma2(u64 a, u64 b, u64 c) {
    u64 d; asm("fma.rn.f32x2 %0,%1,%2,%3;" : "=l"(d) : "l"(a), "l"(b), "l"(c)); return d;
}
__device__ __forceinline__ u64 mul2(u64 a, u64 b) {
    u64 d; asm("mul.rn.f32x2 %0,%1,%2;" : "=l"(d) : "l"(a), "l"(b)); return d;
}
// swap halves (re,im) -> (im,re): lowers to register-pair MOVs on the alu pipe
__device__ __forceinline__ u64 swp(u64 v) {
    float x, y; upk(v, x, y); return pk(y, x);
}

// RY(theta): [[c,-s],[s,c]] (real) acting on complex pair -> fully packed.
template <int M>
__device__ __forceinline__ void ry_gate(u64* st, u64 c2, u64 s2, u64 ns2) {
#pragma unroll
    for (int i = 0; i < 16; i++) {
        if (!(i & M)) {
            u64 a = st[i], b = st[i | M];
            st[i]     = fma2(c2, a, mul2(ns2, b));   // c*a - s*b
            st[i | M] = fma2(s2, a, mul2(c2,  b));   // s*a + c*b
        }
    }
}

// RX(theta): [[c,-is],[-is,c]].
//   a'.re = c*a.re + s*b.im ; a'.im = c*a.im - s*b.re
//   b'.re = c*b.re + s*a.im ; b'.im = c*b.im - s*a.re
// spm = (s, -s); use swapped partner.
template <int M>
__device__ __forceinline__ void rx_gate(u64* st, u64 c2, u64 spm) {
#pragma unroll
    for (int i = 0; i < 16; i++) {
        if (!(i & M)) {
            u64 a = st[i], b = st[i | M];
            st[i]     = fma2(c2, a, mul2(spm, swp(b)));
            st[i | M] = fma2(c2, b, mul2(spm, swp(a)));
        }
    }
}

// CNOT(control mask MC, target mask MT): pure register rename when unrolled.
template <int MC, int MT>
__device__ __forceinline__ void cnot(u64* st) {
#pragma unroll
    for (int i = 0; i < 16; i++) {
        if ((i & MC) && !(i & MT)) {
            u64 t = st[i]; st[i] = st[i | MT]; st[i | MT] = t;
        }
    }
}

__global__ void __launch_bounds__(256)
qdqn_kernel(const float* __restrict__ x,
            const float* __restrict__ wts,   // (5,4)
            const float* __restrict__ Wm,    // (2,4)
            const float* __restrict__ bv,    // (2,)
            float* __restrict__ out,         // (B,2)
            int B)
{
    const int t = blockIdx.x * blockDim.x + threadIdx.x;
    if (t >= B) return;

    // --- per-sample embedding angles (same RY reused every layer) ---
    const float4 xv = reinterpret_cast<const float4*>(x)[t];
    const float xs[4]   = {xv.x, xv.y, xv.z, xv.w};
    const float invb[4] = {1.0f / 4.8f, 1.0f / 4.0f, 1.0f / 0.418f, 1.0f / 4.0f};

    u64 c2y[4], s2y[4], ns2y[4];
#pragma unroll
    for (int q = 0; q < 4; q++) {
        float xn = fminf(fmaxf(xs[q] * invb[q], -1.0f), 1.0f);
        float h  = xn * 1.57079632679489662f;       // (x_norm * pi) / 2
        float s, c;
        __sincosf(h, &s, &c);
        c2y[q]  = pk(c,  c);
        s2y[q]  = pk(s,  s);
        ns2y[q] = pk(-s, -s);
    }

    // --- |0000> ---
    u64 st[16];
#pragma unroll
    for (int i = 0; i < 16; i++) st[i] = 0ull;
    st[0] = pk(1.0f, 0.0f);

    // --- 5 layers: 4x RY (data reupload), 4x RX (weights), CNOT ring ---
#pragma unroll 1
    for (int l = 0; l < 5; l++) {
        ry_gate<8>(st, c2y[0], s2y[0], ns2y[0]);
        ry_gate<4>(st, c2y[1], s2y[1], ns2y[1]);
        ry_gate<2>(st, c2y[2], s2y[2], ns2y[2]);
        ry_gate<1>(st, c2y[3], s2y[3], ns2y[3]);

        const float* wl = wts + l * 4;
        {
            float sw, cw; __sincosf(0.5f * wl[0], &sw, &cw);
            rx_gate<8>(st, pk(cw, cw), pk(sw, -sw));
        }
        {
            float sw, cw; __sincosf(0.5f * wl[1], &sw, &cw);
            rx_gate<4>(st, pk(cw, cw), pk(sw, -sw));
        }
        {
            float sw, cw; __sincosf(0.5f * wl[2], &sw, &cw);
            rx_gate<2>(st, pk(cw, cw), pk(sw, -sw));
        }
        {
            float sw, cw; __sincosf(0.5f * wl[3], &sw, &cw);
            rx_gate<1>(st, pk(cw, cw), pk(sw, -sw));
        }

        cnot<8, 4>(st);   // (0,1)
        cnot<4, 2>(st);   // (1,2)
        cnot<2, 1>(st);   // (2,3)
        cnot<1, 8>(st);   // (3,0)
    }

    // --- probabilities, Z expectations, linear head ---
    float p[16];
#pragma unroll
    for (int i = 0; i < 16; i++) {
        float re, im; upk(st[i], re, im);
        p[i] = fmaf(re, re, im * im);
    }

    float f0 = 0.0f, f1 = 0.0f, f2 = 0.0f, f3 = 0.0f;
#pragma unroll
    for (int i = 0; i < 16; i++) {
        f0 = (i & 8) ? (f0 - p[i]) : (f0 + p[i]);
        f1 = (i & 4) ? (f1 - p[i]) : (f1 + p[i]);
        f2 = (i & 2) ? (f2 - p[i]) : (f2 + p[i]);
        f3 = (i & 1) ? (f3 - p[i]) : (f3 + p[i]);
    }

    float o0 = bv[0];
    o0 = fmaf(Wm[0], f0, o0);
    o0 = fmaf(Wm[1], f1, o0);
    o0 = fmaf(Wm[2], f2, o0);
    o0 = fmaf(Wm[3], f3, o0);
    float o1 = bv[1];
    o1 = fmaf(Wm[4], f0, o1);
    o1 = fmaf(Wm[5], f1, o1);
    o1 = fmaf(Wm[6], f2, o1);
    o1 = fmaf(Wm[7], f3, o1);

    float2 ov; ov.x = o0; ov.y = o1;
    reinterpret_cast<float2*>(out)[t] = ov;
}

extern "C" void kernel_launch(void* const* d_in, const int* in_sizes, int n_in,
                              void* d_out, int out_size) {
    const float* x   = (const float*)d_in[0];  // (B,4)
    const float* wts = (const float*)d_in[1];  // (5,4)
    const float* Wm  = (const float*)d_in[2];  // (2,4)
    const float* bv  = (const float*)d_in[3];  // (2,)
    float* out = (float*)d_out;                // (B,2)

    const int B = in_sizes[0] / 4;
    const int threads = 256;
    const int blocks = (B + threads - 1) / threads;
    qdqn_kernel<<<blocks, threads>>>(x, wts, Wm, bv, out, B);
}

// round 15
// speedup vs baseline: 1.0100x; 1.0100x over previous
#include <cuda_runtime.h>

// ---------------------------------------------------------------------------
// 4-qubit, 5-layer data-reuploading circuit, one sample per thread.
// State: 16 complex amplitudes, each packed (re,im) into a 64-bit f32x2 reg
// pair. All gate math uses Blackwell packed fma.rn.f32x2 / mul.rn.f32x2.
// Qubit q (wire 0 = MSB) maps to index bit mask (8 >> q).
// ---------------------------------------------------------------------------

typedef unsigned long long u64;

__device__ __forceinline__ u64 pk(float x, float y) {
    u64 r; asm("mov.b64 %0,{%1,%2};" : "=l"(r) : "f"(x), "f"(y)); return r;
}
__device__ __forceinline__ void upk(u64 v, float& x, float& y) {
    asm("mov.b64 {%0,%1},%2;" : "=f"(x), "=f"(y) : "l"(v));
}
__device__ __forceinline__ u64 fma2(u64 a, u64 b, u64 c) {
    u64 d; asm("fma.rn.f32x2 %0,%1,%2,%3;" : "=l"(d) : "l"(a), "l"(b), "l"(c)); return d;
}
__device__ __forceinline__ u64 mul2(u64 a, u64 b) {
    u64 d; asm("mul.rn.f32x2 %0,%1,%2;" : "=l"(d) : "l"(a), "l"(b)); return d;
}
// swap halves (re,im) -> (im,re): lowers to register-pair MOVs on the alu pipe
__device__ __forceinline__ u64 swp(u64 v) {
    float x, y; upk(v, x, y); return pk(y, x);
}

// RY(theta): [[c,-s],[s,c]] (real) acting on complex pair -> fully packed.
template <int M>
__device__ __forceinline__ void ry_gate(u64* st, u64 c2, u64 s2, u64 ns2) {
#pragma unroll
    for (int i = 0; i < 16; i++) {
        if (!(i & M)) {
            u64 a = st[i], b = st[i | M];
            st[i]     = fma2(c2, a, mul2(ns2, b));   // c*a - s*b
            st[i | M] = fma2(s2, a, mul2(c2,  b));   // s*a + c*b
        }
    }
}

// RX(theta): [[c,-is],[-is,c]].
//   a'.re = c*a.re + s*b.im ; a'.im = c*a.im - s*b.re
//   b'.re = c*b.re + s*a.im ; b'.im = c*b.im - s*a.re
// spm = (s, -s); use swapped partner.
template <int M>
__device__ __forceinline__ void rx_gate(u64* st, u64 c2, u64 spm) {
#pragma unroll
    for (int i = 0; i < 16; i++) {
        if (!(i & M)) {
            u64 a = st[i], b = st[i | M];
            st[i]     = fma2(c2, a, mul2(spm, swp(b)));
            st[i | M] = fma2(c2, b, mul2(spm, swp(a)));
        }
    }
}

// CNOT(control mask MC, target mask MT): pure register rename when unrolled.
template <int MC, int MT>
__device__ __forceinline__ void cnot(u64* st) {
#pragma unroll
    for (int i = 0; i < 16; i++) {
        if ((i & MC) && !(i & MT)) {
            u64 t = st[i]; st[i] = st[i | MT]; st[i | MT] = t;
        }
    }
}

__global__ void __launch_bounds__(256)
qdqn_kernel(const float* __restrict__ x,
            const float* __restrict__ wts,   // (5,4)
            const float* __restrict__ Wm,    // (2,4)
            const float* __restrict__ bv,    // (2,)
            float* __restrict__ out,         // (B,2)
            int B)
{
    const int t = blockIdx.x * blockDim.x + threadIdx.x;
    if (t >= B) return;

    // --- per-sample embedding angles (same RY reused every layer) ---
    const float4 xv = reinterpret_cast<const float4*>(x)[t];
    const float xs[4]   = {xv.x, xv.y, xv.z, xv.w};
    const float invb[4] = {1.0f / 4.8f, 1.0f / 4.0f, 1.0f / 0.418f, 1.0f / 4.0f};

    u64 c2y[4], s2y[4], ns2y[4];
#pragma unroll
    for (int q = 0; q < 4; q++) {
        float xn = fminf(fmaxf(xs[q] * invb[q], -1.0f), 1.0f);
        float h  = xn * 1.57079632679489662f;       // (x_norm * pi) / 2
        float s, c;
        __sincosf(h, &s, &c);
        c2y[q]  = pk(c,  c);
        s2y[q]  = pk(s,  s);
        ns2y[q] = pk(-s, -s);
    }

    // --- |0000> ---
    u64 st[16];
#pragma unroll
    for (int i = 0; i < 16; i++) st[i] = 0ull;
    st[0] = pk(1.0f, 0.0f);

    // --- 5 layers: 4x RY (data reupload), 4x RX (weights), CNOT ring ---
#pragma unroll 1
    for (int l = 0; l < 5; l++) {
        ry_gate<8>(st, c2y[0], s2y[0], ns2y[0]);
        ry_gate<4>(st, c2y[1], s2y[1], ns2y[1]);
        ry_gate<2>(st, c2y[2], s2y[2], ns2y[2]);
        ry_gate<1>(st, c2y[3], s2y[3], ns2y[3]);

        const float* wl = wts + l * 4;
        {
            float sw, cw; __sincosf(0.5f * wl[0], &sw, &cw);
            rx_gate<8>(st, pk(cw, cw), pk(sw, -sw));
        }
        {
            float sw, cw; __sincosf(0.5f * wl[1], &sw, &cw);
            rx_gate<4>(st, pk(cw, cw), pk(sw, -sw));
        }
        {
            float sw, cw; __sincosf(0.5f * wl[2], &sw, &cw);
            rx_gate<2>(st, pk(cw, cw), pk(sw, -sw));
        }
        {
            float sw, cw; __sincosf(0.5f * wl[3], &sw, &cw);
            rx_gate<1>(st, pk(cw, cw), pk(sw, -sw));
        }

        cnot<8, 4>(st);   // (0,1)
        cnot<4, 2>(st);   // (1,2)
        cnot<2, 1>(st);   // (2,3)
        cnot<1, 8>(st);   // (3,0)
    }

    // --- probabilities, Z expectations, linear head ---
    float p[16];
#pragma unroll
    for (int i = 0; i < 16; i++) {
        float re, im; upk(st[i], re, im);
        p[i] = fmaf(re, re, im * im);
    }

    float f0 = 0.0f, f1 = 0.0f, f2 = 0.0f, f3 = 0.0f;
#pragma unroll
    for (int i = 0; i < 16; i++) {
        f0 = (i & 8) ? (f0 - p[i]) : (f0 + p[i]);
        f1 = (i & 4) ? (f1 - p[i]) : (f1 + p[i]);
        f2 = (i & 2) ? (f2 - p[i]) : (f2 + p[i]);
        f3 = (i & 1) ? (f3 - p[i]) : (f3 + p[i]);
    }

    float o0 = bv[0];
    o0 = fmaf(Wm[0], f0, o0);
    o0 = fmaf(Wm[1], f1, o0);
    o0 = fmaf(Wm[2], f2, o0);
    o0 = fmaf(Wm[3], f3, o0);
    float o1 = bv[1];
    o1 = fmaf(Wm[4], f0, o1);
    o1 = fmaf(Wm[5], f1, o1);
    o1 = fmaf(Wm[6], f2, o1);
    o1 = fmaf(Wm[7], f3, o1);

    float2 ov; ov.x = o0; ov.y = o1;
    reinterpret_cast<float2*>(out)[t] = ov;
}

extern "C" void kernel_launch(void* const* d_in, const int* in_sizes, int n_in,
                              void* d_out, int out_size) {
    const float* x   = (const float*)d_in[0];  // (B,4)
    const float* wts = (const float*)d_in[1];  // (5,4)
    const float* Wm  = (const float*)d_in[2];  // (2,4)
    const float* bv  = (const float*)d_in[3];  // (2,)
    float* out = (float*)d_out;                // (B,2)

    const int B = in_sizes[0] / 4;
    const int threads = 256;
    const int blocks = (B + threads - 1) / threads;
    qdqn_kernel<<<blocks, threads>>>(x, wts, Wm, bv, out, B);
}